// round 2
// baseline (speedup 1.0000x reference)
#include <cuda_runtime.h>

// ---------------------------------------------------------------------------
// Problem constants
// ---------------------------------------------------------------------------
#define EPSF 1e-8f

constexpr int NQ = 8192;     // queries
constexpr int NK = 524288;   // keys
constexpr int D  = 128;      // head_dim
constexpr int NF = 64;       // num_freqs
constexpr int NB = 128;      // num_bins
constexpr int DT = 192;      // D + NF  (GEMM K-dimension: K values ++ K magnitudes)

// ---------------------------------------------------------------------------
// Device scratch (no allocations allowed)
// ---------------------------------------------------------------------------
__device__ float  g_W[DT * NB];      // W[k][b]: k<128 -> rotated_probes[b][k]; k>=128 -> kmw[b][k-128]
__device__ float2 g_rpq[NF * NB];    // rotated probe pairs, [f][b]
__device__ float  g_effw[NF * NB];   // -softplus(q_weights_raw), [f][b]
__device__ float  g_qmw[NF * NB];    // q_magnitude_weights, [f][b]

// ---------------------------------------------------------------------------
// Helpers
// ---------------------------------------------------------------------------
typedef unsigned long long ull;

__device__ __forceinline__ float sqrt_approx(float x) {
    float y;
    asm("sqrt.approx.f32 %0, %1;" : "=f"(y) : "f"(x));
    return y;
}

__device__ __forceinline__ ull pack2(float lo, float hi) {
    ull r;
    asm("mov.b64 %0, {%1, %2};" : "=l"(r) : "f"(lo), "f"(hi));
    return r;
}

__device__ __forceinline__ float2 unpack2(ull v) {
    float2 r;
    asm("mov.b64 {%0, %1}, %2;" : "=f"(r.x), "=f"(r.y) : "l"(v));
    return r;
}

// packed dual-FMA: d.lo += a.lo*b.lo ; d.hi += a.hi*b.hi   (Blackwell f32x2 pipe)
__device__ __forceinline__ void ffma2(ull& d, ull a, ull b) {
    asm("fma.rn.f32x2 %0, %1, %2, %0;" : "+l"(d) : "l"(a), "l"(b));
}

// ---------------------------------------------------------------------------
// Prep kernel: rotated probes + transposed weight tables (1 block, 128 thr)
// ---------------------------------------------------------------------------
__global__ void prep_kernel(const float* __restrict__ angles,
                            const float* __restrict__ probes,
                            const float* __restrict__ kmw,
                            const float* __restrict__ qraw,
                            const float* __restrict__ qmw)
{
    __shared__ float sc[NF], ss[NF];
    const int b = threadIdx.x;  // 0..127 = bin
    if (b < NF) {
        float a = angles[b];
        sc[b] = cosf(a);
        ss[b] = sinf(a);
    }
    __syncthreads();

    float sum = 0.0f;
    #pragma unroll 4
    for (int d = 0; d < D; d++) {
        float v = probes[b * D + d];
        sum = fmaf(v, v, sum);
    }
    float inv = 1.0f / (sqrtf(sum) + EPSF);

    for (int f = 0; f < NF; f++) {
        float p0 = probes[b * D + 2 * f]     * inv;
        float p1 = probes[b * D + 2 * f + 1] * inv;
        float r0 = p0 * sc[f] - p1 * ss[f];
        float r1 = p0 * ss[f] + p1 * sc[f];
        g_W[(2 * f)     * NB + b] = r0;
        g_W[(2 * f + 1) * NB + b] = r1;
        g_rpq[f * NB + b] = make_float2(r0, r1);
        g_W[(D + f) * NB + b] = kmw[b * NF + f];

        float x  = qraw[b * NF + f];
        float sp = fmaxf(x, 0.0f) + log1pf(expf(-fabsf(x)));
        g_effw[f * NB + b] = -sp;
        g_qmw[f * NB + b]  = qmw[b * NF + f];
    }
}

// ---------------------------------------------------------------------------
// K path: k_logits[r][b] = sum_k A[r][k] * W[k][b] + k_bias[b]
//   A[r][0..127]   = K[r][:]
//   A[r][128..191] = sqrt(K[r][2f]^2 + K[r][2f+1]^2 + eps)
// Tiled GEMM, weights resident in smem, packed f32x2 FMA (bins paired).
// ---------------------------------------------------------------------------
constexpr int TILE_M          = 128;
constexpr int KTHREADS        = 256;
constexpr int TILES_PER_BLOCK = 4;
constexpr int SA_STRIDE       = 193;   // odd stride -> conflict-free row access

__global__ void __launch_bounds__(KTHREADS, 1)
kpath_kernel(const float* __restrict__ Kmat,
             const float* __restrict__ kbias,
             float* __restrict__ out)
{
    extern __shared__ float smem[];
    float* sW = smem;                       // DT*NB          = 24576 floats
    float* sA = sW + DT * NB;               // TILE_M*193     = 24704 floats
    float* sB = sA + TILE_M * SA_STRIDE;    // NB             = 128 floats

    const int tid = threadIdx.x;
    const int tx  = tid & 7;    // bin-pair lane: bins b = i*16 + tx*2, i=0..7
    const int ty  = tid >> 3;   // 0..31 -> rows ty*4 .. ty*4+3

    // Load weight matrix + bias once per block
    for (int i = tid; i < DT * NB; i += KTHREADS) sW[i] = g_W[i];
    if (tid < NB) sB[tid] = kbias[tid];

    const int r0off = (ty * 4 + 0) * SA_STRIDE;
    const int r1off = (ty * 4 + 1) * SA_STRIDE;
    const int r2off = (ty * 4 + 2) * SA_STRIDE;
    const int r3off = (ty * 4 + 3) * SA_STRIDE;
    const ull* wbase = reinterpret_cast<const ull*>(sW) + tx;  // ull idx = k*64 + i*8 + tx

    for (int t = 0; t < TILES_PER_BLOCK; t++) {
        const int rowBase = (blockIdx.x * TILES_PER_BLOCK + t) * TILE_M;
        __syncthreads();  // sW/sB ready on first iter; sA free of readers on later iters

        // Stage K tile (float4, fully coalesced)
        const float4* K4 = reinterpret_cast<const float4*>(Kmat) + (size_t)rowBase * (D / 4);
        for (int i = tid; i < TILE_M * (D / 4); i += KTHREADS) {
            int row = i >> 5, c4 = i & 31;
            float4 v = K4[row * (D / 4) + c4];
            float* dst = sA + row * SA_STRIDE + c4 * 4;
            dst[0] = v.x; dst[1] = v.y; dst[2] = v.z; dst[3] = v.w;
        }
        __syncthreads();

        // Magnitude columns
        for (int i = tid; i < TILE_M * NF; i += KTHREADS) {
            int row = i >> 6, f = i & 63;
            float a0 = sA[row * SA_STRIDE + 2 * f];
            float a1 = sA[row * SA_STRIDE + 2 * f + 1];
            sA[row * SA_STRIDE + D + f] = sqrt_approx(fmaf(a0, a0, fmaf(a1, a1, EPSF)));
        }
        __syncthreads();

        // GEMM: 4 rows x 16 bins per thread, bins packed as f32x2 pairs
        ull acc[4][8];
        #pragma unroll
        for (int r = 0; r < 4; r++)
            #pragma unroll
            for (int i = 0; i < 8; i++) acc[r][i] = 0ull;

        #pragma unroll 2
        for (int k = 0; k < DT; k++) {
            float a0 = sA[r0off + k];
            float a1 = sA[r1off + k];
            float a2 = sA[r2off + k];
            float a3 = sA[r3off + k];
            ull ap0 = pack2(a0, a0);
            ull ap1 = pack2(a1, a1);
            ull ap2 = pack2(a2, a2);
            ull ap3 = pack2(a3, a3);
            const ull* w = wbase + k * 64;
            #pragma unroll
            for (int i = 0; i < 8; i++) {
                ull wp = w[i * 8];
                ffma2(acc[0][i], ap0, wp);
                ffma2(acc[1][i], ap1, wp);
                ffma2(acc[2][i], ap2, wp);
                ffma2(acc[3][i], ap3, wp);
            }
        }

        // Epilogue: bias + store
        #pragma unroll
        for (int r = 0; r < 4; r++) {
            const int grow = rowBase + ty * 4 + r;
            float* orow = out + (size_t)grow * NB;
            #pragma unroll
            for (int i = 0; i < 8; i++) {
                float2 v = unpack2(acc[r][i]);
                int b0 = i * 16 + tx * 2;
                v.x += sB[b0];
                v.y += sB[b0 + 1];
                *reinterpret_cast<float2*>(orow + b0) = v;
            }
        }
    }
}

// ---------------------------------------------------------------------------
// Q path: q_logits[q][b] = sum_f |rp[b][f] - Qn[q][f]| * effw[b][f]
//                        + sum_f Qmag[q][f] * qmw[b][f] + q_bias[b]
// 32 queries per block, all tables resident in smem.
// ---------------------------------------------------------------------------
constexpr int QTHREADS = 256;
constexpr int QPB      = 32;

__global__ void __launch_bounds__(QTHREADS, 1)
qpath_kernel(const float* __restrict__ Q,
             const float* __restrict__ qbias,
             float* __restrict__ outq)
{
    extern __shared__ float smem[];
    float2* sRP  = reinterpret_cast<float2*>(smem);      // NF*NB float2
    float* sEW   = smem + 2 * NF * NB;                   // NF*NB
    float* sMW   = sEW + NF * NB;                        // NF*NB
    float* sQn   = sMW + NF * NB;                        // QPB*D
    float* sQmag = sQn + QPB * D;                        // QPB*NF
    float* sInv  = sQmag + QPB * NF;                     // QPB
    float* sQB   = sInv + QPB;                           // NB

    const int tid = threadIdx.x;
    for (int i = tid; i < NF * NB; i += QTHREADS) {
        sRP[i] = g_rpq[i];
        sEW[i] = g_effw[i];
        sMW[i] = g_qmw[i];
    }
    if (tid < NB) sQB[tid] = qbias[tid];

    const int qbase = blockIdx.x * QPB;
    for (int i = tid; i < QPB * D; i += QTHREADS)
        sQn[i] = Q[(size_t)qbase * D + i];
    __syncthreads();

    // L2 norms: 8 threads per query
    {
        int q = tid >> 3, l8 = tid & 7;
        float s = 0.0f;
        #pragma unroll
        for (int j = 0; j < D / 8; j++) {
            float v = sQn[q * D + l8 + 8 * j];
            s = fmaf(v, v, s);
        }
        s += __shfl_down_sync(0xffffffffu, s, 4, 8);
        s += __shfl_down_sync(0xffffffffu, s, 2, 8);
        s += __shfl_down_sync(0xffffffffu, s, 1, 8);
        if (l8 == 0) sInv[q] = 1.0f / (sqrtf(s) + EPSF);
    }
    __syncthreads();
    for (int i = tid; i < QPB * D; i += QTHREADS)
        sQn[i] *= sInv[i >> 7];
    __syncthreads();
    for (int i = tid; i < QPB * NF; i += QTHREADS) {
        int q = i >> 6, f = i & 63;
        float a = sQn[q * D + 2 * f];
        float c = sQn[q * D + 2 * f + 1];
        sQmag[i] = sqrt_approx(fmaf(a, a, fmaf(c, c, EPSF)));
    }
    __syncthreads();

    const int b  = tid & 127;
    const int qg = tid >> 7;    // 0/1: 16 queries each
    float acc[16];
    #pragma unroll
    for (int j = 0; j < 16; j++) acc[j] = 0.0f;

    for (int f = 0; f < NF; f++) {
        float2 rp = sRP[f * NB + b];
        float  ew = sEW[f * NB + b];
        float  mw = sMW[f * NB + b];
        #pragma unroll
        for (int j = 0; j < 16; j++) {
            int q = qg * 16 + j;
            float2 qp = *reinterpret_cast<const float2*>(sQn + q * D + 2 * f);
            float d0 = rp.x - qp.x;
            float d1 = rp.y - qp.y;
            float dist = sqrt_approx(fmaf(d0, d0, fmaf(d1, d1, EPSF)));
            acc[j] = fmaf(dist, ew, acc[j]);
            acc[j] = fmaf(sQmag[q * NF + f], mw, acc[j]);
        }
    }

    #pragma unroll
    for (int j = 0; j < 16; j++) {
        int q = qbase + qg * 16 + j;
        outq[(size_t)q * NB + b] = acc[j] + sQB[b];
    }
}

// ---------------------------------------------------------------------------
// Launch
// ---------------------------------------------------------------------------
extern "C" void kernel_launch(void* const* d_in, const int* in_sizes, int n_in,
                              void* d_out, int out_size)
{
    const float* Q      = (const float*)d_in[0];
    const float* Kmat   = (const float*)d_in[1];
    const float* angles = (const float*)d_in[2];
    const float* probes = (const float*)d_in[3];
    const float* kmw    = (const float*)d_in[4];
    const float* kbias  = (const float*)d_in[5];
    const float* qraw   = (const float*)d_in[6];
    const float* qmw    = (const float*)d_in[7];
    const float* qbias  = (const float*)d_in[8];
    float* out = (float*)d_out;

    const size_t smemK = (size_t)(DT * NB + TILE_M * SA_STRIDE + NB) * sizeof(float);   // 197,632 B
    const size_t smemQ = (size_t)(2 * NF * NB + NF * NB + NF * NB + QPB * D + QPB * NF
                                  + QPB + NB) * sizeof(float);                          // 156,288 B

    cudaFuncSetAttribute(kpath_kernel, cudaFuncAttributeMaxDynamicSharedMemorySize, (int)smemK);
    cudaFuncSetAttribute(qpath_kernel, cudaFuncAttributeMaxDynamicSharedMemorySize, (int)smemQ);

    prep_kernel<<<1, 128>>>(angles, probes, kmw, qraw, qmw);
    kpath_kernel<<<NK / (TILE_M * TILES_PER_BLOCK), KTHREADS, smemK>>>(Kmat, kbias, out);
    qpath_kernel<<<NQ / QPB, QTHREADS, smemQ>>>(Q, qbias, out + (size_t)NK * NB);
}